// round 1
// baseline (speedup 1.0000x reference)
#include <cuda_runtime.h>
#include <cuda_bf16.h>

// Problem constants
#define BATCH 2
#define SEQ   2048
#define DIM   1024
#define NH    16
#define JCHUNK 128
#define NJC   (SEQ / JCHUNK)   // 16

// Scratch (allocation-free: __device__ globals)
__device__ float g_part[NJC][BATCH][DIM];   // partial column sums of masked x
__device__ float g_sum[BATCH][DIM];         // full column sums
__device__ float g_vmean[BATCH][DIM];       // (meanX) @ Wv.T
__device__ float g_orow[BATCH][DIM];        // g_vmean @ Wo.T  (one output row per batch)
__device__ float g_row[BATCH][SEQ];         // attn row template: mask ? 1/cnt : 0
__device__ float g_inv[BATCH];              // 1/cnt per batch

// ---------------------------------------------------------------------------
// 1) Count mask per batch, build inv_cnt and the attn row template.
//    grid(BATCH), block(1024)
// ---------------------------------------------------------------------------
__global__ void k_init(const int* __restrict__ mask) {
    int b = blockIdx.x;
    int t = threadIdx.x;                    // 0..1023
    __shared__ int red[32];

    int m0 = mask[b * SEQ + t];
    int m1 = mask[b * SEQ + 1024 + t];
    int c  = m0 + m1;
    #pragma unroll
    for (int o = 16; o; o >>= 1) c += __shfl_down_sync(0xFFFFFFFFu, c, o);
    if ((t & 31) == 0) red[t >> 5] = c;
    __syncthreads();
    if (t < 32) {
        int v = red[t];
        #pragma unroll
        for (int o = 16; o; o >>= 1) v += __shfl_down_sync(0xFFFFFFFFu, v, o);
        if (t == 0) g_inv[b] = 1.0f / (float)v;
    }
    __syncthreads();                        // makes g_inv[b] visible block-wide
    float inv = g_inv[b];
    g_row[b][t]        = m0 ? inv : 0.0f;
    g_row[b][1024 + t] = m1 ? inv : 0.0f;
}

// ---------------------------------------------------------------------------
// 2) Masked column sums of x, deterministic two-stage (no float atomics).
//    grid(DIM/256, NJC, BATCH), block(256)
// ---------------------------------------------------------------------------
__global__ void k_colsum(const float* __restrict__ x, const int* __restrict__ mask) {
    int d  = blockIdx.x * 256 + threadIdx.x;
    int jc = blockIdx.y;
    int b  = blockIdx.z;
    const float* xp = x + ((long)b * SEQ + (long)jc * JCHUNK) * DIM + d;
    const int*   mp = mask + b * SEQ + jc * JCHUNK;
    float acc = 0.0f;
    #pragma unroll 8
    for (int j = 0; j < JCHUNK; j++)
        acc += mp[j] ? xp[(long)j * DIM] : 0.0f;
    g_part[jc][b][d] = acc;
}

// grid(DIM/256, BATCH), block(256)
__global__ void k_reduce() {
    int d = blockIdx.x * 256 + threadIdx.x;
    int b = blockIdx.y;
    float a = 0.0f;
    #pragma unroll
    for (int jc = 0; jc < NJC; jc++) a += g_part[jc][b][d];
    g_sum[b][d] = a;
}

// ---------------------------------------------------------------------------
// 3) Matvec: vout[b][o] = (optional inv) * sum_d vin[b][d] * W[o*DIM + d]
//    mode 0: g_sum  -> g_vmean (apply inv)       [W = Wv]
//    mode 1: g_vmean -> g_orow                   [W = Wo]
//    grid(DIM/8, BATCH), block(256) — one warp per output o
// ---------------------------------------------------------------------------
__global__ void k_matvec(const float* __restrict__ W, int mode) {
    int warp = threadIdx.x >> 5;
    int lane = threadIdx.x & 31;
    int o = blockIdx.x * 8 + warp;
    int b = blockIdx.y;

    const float* vi = (mode == 0) ? g_sum[b] : g_vmean[b];
    const float* w  = W + (long)o * DIM;
    float acc = 0.0f;
    #pragma unroll
    for (int k = 0; k < DIM / 32; k++)
        acc += vi[lane + 32 * k] * w[lane + 32 * k];
    #pragma unroll
    for (int off = 16; off; off >>= 1) acc += __shfl_down_sync(0xFFFFFFFFu, acc, off);
    if (lane == 0) {
        if (mode == 0) g_vmean[b][o] = acc * g_inv[b];
        else           g_orow[b][o]  = acc;
    }
}

// ---------------------------------------------------------------------------
// 4) Broadcast fills (bandwidth-bound bulk). float4 stores.
// ---------------------------------------------------------------------------
// out[b, i, d] = g_orow[b][d].  base index = b*2^21 + i*2^10 + d
__global__ void k_fill_out(float* __restrict__ out) {
    long base = ((long)blockIdx.x * blockDim.x + threadIdx.x) * 4;
    int d = (int)(base & (DIM - 1));
    int b = (int)(base >> 21);              // SEQ*DIM = 2^21
    float4 v = *(const float4*)&g_orow[b][d];
    *(float4*)(out + base) = v;
}

// attn[h, b, i, j] = g_row[b][j].  index = h*2^23 + b*2^22 + i*2^11 + j
__global__ void k_fill_attn(float* __restrict__ attn) {
    long base = ((long)blockIdx.x * blockDim.x + threadIdx.x) * 4;
    int j = (int)(base & (SEQ - 1));
    int b = (int)((base >> 22) & (BATCH - 1));   // SEQ*SEQ = 2^22
    float4 v = *(const float4*)&g_row[b][j];
    *(float4*)(attn + base) = v;
}

// ---------------------------------------------------------------------------
// Launch
// ---------------------------------------------------------------------------
extern "C" void kernel_launch(void* const* d_in, const int* in_sizes, int n_in,
                              void* d_out, int out_size) {
    const float* x    = (const float*)d_in[0];
    const int*   mask = (const int*)  d_in[1];
    // d_in[2] = Wq, d_in[3] = Wk — mathematically irrelevant (softmax collapses)
    const float* Wv   = (const float*)d_in[4];
    const float* Wo   = (const float*)d_in[5];

    const long OUT_E  = (long)BATCH * SEQ * DIM;        //   4,194,304
    const long ATTN_E = (long)NH * BATCH * SEQ * SEQ;   // 134,217,728

    float* out_ptr  = nullptr;
    float* attn_ptr = nullptr;
    long osz = (long)(unsigned)out_size;
    if (osz >= OUT_E + ATTN_E) {            // tuple flattened: out then attn
        out_ptr  = (float*)d_out;
        attn_ptr = (float*)d_out + OUT_E;
    } else if (osz == ATTN_E) {
        attn_ptr = (float*)d_out;
    } else {
        out_ptr  = (float*)d_out;
    }

    k_init<<<BATCH, 1024>>>(mask);
    k_colsum<<<dim3(DIM / 256, NJC, BATCH), 256>>>(x, mask);
    k_reduce<<<dim3(DIM / 256, BATCH), 256>>>();
    k_matvec<<<dim3(DIM / 8, BATCH), 256>>>(Wv, 0);
    k_matvec<<<dim3(DIM / 8, BATCH), 256>>>(Wo, 1);

    if (out_ptr)
        k_fill_out<<<(unsigned)(OUT_E / 4 / 256), 256>>>(out_ptr);
    if (attn_ptr)
        k_fill_attn<<<(unsigned)(ATTN_E / 4 / 256), 256>>>(attn_ptr);
}